// round 16
// baseline (speedup 1.0000x reference)
#include <cuda_runtime.h>
#include <cuda_fp16.h>
#include <math.h>
#include <stdint.h>

#define NH   16
#define NKV  4
#define HD   128
#define HIDD 2048
#define FFI  8192
#define QKVW ((NH + 2*NKV) * HD)   /* 3072 */

// ================= scratch (B=4, S=1024) =================
static __device__ float g_h1[4096L * HIDD];

static __device__ __half g_h[4096L * HIDD];
static __device__ __half g_ao[4096L * HIDD];
static __device__ __half g_act[4096L * FFI];
static __device__ __half g_q[(long)4*NH*1024*HD];
static __device__ __half g_k[(long)4*NKV*1024*HD];
static __device__ __half g_vt[(long)4*NKV*HD*1024];
static __device__ __half g_wqkvH[(long)HIDD * QKVW];   /* [K,N] native */
static __device__ __half g_woH[(long)HIDD * HIDD];
static __device__ __half g_guH[(long)HIDD * 2*FFI];    /* [K,N], gate/up 8-block interleaved */
static __device__ __half g_dnH[(long)FFI * HIDD];

// ================= PTX helpers =================
__device__ __forceinline__ uint32_t smem_u32(const void* p) {
    uint32_t a;
    asm("{ .reg .u64 t; cvta.to.shared.u64 t, %1; cvt.u32.u64 %0, t; }" : "=r"(a) : "l"(p));
    return a;
}
__device__ __forceinline__ void cp16(uint32_t dst, const void* src) {
    asm volatile("cp.async.cg.shared.global [%0], [%1], 16;" :: "r"(dst), "l"(src));
}
__device__ __forceinline__ void cp_commit() { asm volatile("cp.async.commit_group;"); }
__device__ __forceinline__ void cp_wait2() { asm volatile("cp.async.wait_group 2;"); }
__device__ __forceinline__ void cp_wait1() { asm volatile("cp.async.wait_group 1;"); }
__device__ __forceinline__ void cp_wait0() { asm volatile("cp.async.wait_group 0;"); }

__device__ __forceinline__ void ldm_x4(uint32_t* r, uint32_t addr) {
    asm volatile("ldmatrix.sync.aligned.m8n8.x4.shared.b16 {%0,%1,%2,%3}, [%4];"
        : "=r"(r[0]), "=r"(r[1]), "=r"(r[2]), "=r"(r[3]) : "r"(addr));
}
__device__ __forceinline__ void ldm_x4t(uint32_t* r, uint32_t addr) {
    asm volatile("ldmatrix.sync.aligned.m8n8.x4.trans.shared.b16 {%0,%1,%2,%3}, [%4];"
        : "=r"(r[0]), "=r"(r[1]), "=r"(r[2]), "=r"(r[3]) : "r"(addr));
}
__device__ __forceinline__ void mma16816h(float* d, const uint32_t* a, const uint32_t* b) {
    asm volatile("mma.sync.aligned.m16n8k16.row.col.f32.f16.f16.f32 "
        "{%0,%1,%2,%3}, {%4,%5,%6,%7}, {%8,%9}, {%0,%1,%2,%3};"
        : "+f"(d[0]), "+f"(d[1]), "+f"(d[2]), "+f"(d[3])
        : "r"(a[0]), "r"(a[1]), "r"(a[2]), "r"(a[3]), "r"(b[0]), "r"(b[1]));
}
__device__ __forceinline__ float silu_mul(float g, float u) {
    return (g / (1.f + __expf(-g))) * u;
}
__device__ __forceinline__ uint32_t pack_h2(float a, float b) {
    __half2 h = __floats2half2_rn(a, b);
    return *(uint32_t*)&h;
}

// ================= fp16 GEMM (A: [M,K] row-major; B: [K,N] row-major via ldmatrix.trans) =================
// MODE 0: weights (fp32 out, optional residual, block swizzle)
// MODE 3: gate_up (8-block-interleaved B cols; epilogue silu(gate)*up -> fp16, block swizzle)
// MODE 4: qkv     (epilogue stages tile to smem; RoPE+split q/k (+1/sqrt(D) on q), transpose v)
#define SAS 72
#define ATILEB (128 * SAS * 2)    /* 18432 */
#define BSTR 136                  /* B smem row stride (halves) */
#define BTILEB (64 * BSTR * 2)    /* 17408 */
#define STAGE (ATILEB + BTILEB)   /* 35840 */
#define HG_SMEM (3 * STAGE)       /* 107520, 3-stage pipeline */
#define EPS_ST 133                /* fp32 staging stride; 128*133*4=68096 <= 107520 */

template<int MODE, bool RES>
__global__ void __launch_bounds__(256, 2)
hgemm(const __half* __restrict__ A, const __half* __restrict__ B,
      const float* __restrict__ R, float* __restrict__ Cf, __half* __restrict__ Ch,
      __half* __restrict__ Ck, __half* __restrict__ Cvt, const int* __restrict__ pos,
      int K, int ldb, int ldc, float qscale, int S)
{
    extern __shared__ char sm[];
    const uint32_t sbase = smem_u32(sm);
    const int tid = threadIdx.x;

    int m0, n0;
    {
        int lin = blockIdx.y * gridDim.x + blockIdx.x;
        int grpSize = gridDim.x * 8;
        int grp = lin / grpSize, rem = lin % grpSize;
        m0 = (rem >> 3) * 128;
        n0 = (grp * 8 + (rem & 7)) * 128;
    }

    const int NB = K >> 6;
    const int wid = tid >> 5, lane = tid & 31;
    const int wm = (wid >> 2) * 64;
    const int wn = (wid & 3) * 32;

    const __half* Asrc = A + (long)m0 * K;
    const __half* Bsrc = B + n0;

    const int alr = lane & 15, alc = (lane >> 4) * 8;
    const int blr = lane & 7;
    const int bhalf = (lane >> 3) & 1;
    const int bquad = (lane >> 4) * 8;

    float acc[4][4][4];
    #pragma unroll
    for (int i = 0; i < 4; i++)
        #pragma unroll
        for (int j = 0; j < 4; j++)
            #pragma unroll
            for (int q = 0; q < 4; q++) acc[i][j][q] = 0.f;

    auto load_stage = [&](int s, int blk) {
        const long kb = (long)blk << 6;
        const uint32_t dA = sbase + s * STAGE;
        #pragma unroll
        for (int i = 0; i < 4; i++) {
            int idx = tid + 256 * i;
            int r = idx >> 3, c = idx & 7;
            cp16(dA + (r * SAS + c * 8) * 2, Asrc + kb + (long)r * K + c * 8);
        }
        const uint32_t dB = dA + ATILEB;
        #pragma unroll
        for (int i = 0; i < 4; i++) {
            int idx = tid + 256 * i;
            int r = idx >> 4, c = idx & 15;   // r: k-row 0..63, c: n-chunk
            cp16(dB + (r * BSTR + c * 8) * 2, Bsrc + (kb + r) * (long)ldb + c * 8);
        }
        cp_commit();
    };

    // 3-stage pipeline prologue (NB >= 2 for all uses)
    load_stage(0, 0);
    load_stage(1, 1);

    int sidx = 0;
    for (int blk = 0; blk < NB; blk++) {
        if (blk + 2 < NB) { load_stage((sidx + 2) % 3, blk + 2); cp_wait2(); }
        else if (blk + 1 < NB) { cp_wait1(); }
        else { cp_wait0(); }
        __syncthreads();

        const uint32_t sA_ = sbase + sidx * STAGE;
        const uint32_t sB_ = sA_ + ATILEB;

        #pragma unroll
        for (int kt = 0; kt < 4; kt++) {
            uint32_t aa[4][4], bb[4][2];
            #pragma unroll
            for (int ma = 0; ma < 4; ma++) {
                uint32_t ao = ((wm + ma * 16 + alr) * SAS + kt * 16 + alc) * 2;
                ldm_x4(aa[ma], sA_ + ao);
            }
            #pragma unroll
            for (int np = 0; np < 2; np++) {
                uint32_t bo = ((kt * 16 + bhalf * 8 + blr) * BSTR + wn + np * 16 + bquad) * 2;
                uint32_t t4[4];
                ldm_x4t(t4, sB_ + bo);
                bb[np*2+0][0] = t4[0]; bb[np*2+0][1] = t4[1];
                bb[np*2+1][0] = t4[2]; bb[np*2+1][1] = t4[3];
            }
            #pragma unroll
            for (int ma = 0; ma < 4; ma++)
                #pragma unroll
                for (int na = 0; na < 4; na++)
                    mma16816h(acc[ma][na], aa[ma], bb[na]);
        }
        __syncthreads();
        sidx = (sidx + 1) % 3;
    }

    const int erow = lane >> 2, ecol = (lane & 3) * 2;

    if (MODE == 4) {
        float* st = (float*)sm;
        #pragma unroll
        for (int ma = 0; ma < 4; ma++) {
            #pragma unroll
            for (int na = 0; na < 4; na++) {
                int rr = wm + ma * 16 + erow;
                int cc = wn + na * 8 + ecol;
                st[rr * EPS_ST + cc]           = acc[ma][na][0];
                st[rr * EPS_ST + cc + 1]       = acc[ma][na][1];
                st[(rr + 8) * EPS_ST + cc]     = acc[ma][na][2];
                st[(rr + 8) * EPS_ST + cc + 1] = acc[ma][na][3];
            }
        }
        __syncthreads();
        const int nt = n0 >> 7;          // 0..15 q, 16..19 k, 20..23 v
        if (nt < NH + NKV) {
            const float sc_ = (nt < NH) ? qscale : 1.f;
            for (int i = tid; i < 128 * 64; i += 256) {
                int rr = i >> 6;
                int d  = i & 63;
                float t1 = st[rr * EPS_ST + d];
                float t2 = st[rr * EPS_ST + d + 64];
                int grow = m0 + rr;
                int b = grow / S, s = grow - b * S;
                float invf = __powf(10000.f, -(float)d * (1.f/64.f));
                float ang = (float)pos[s] * invf;
                float sn, cs;
                __sincosf(ang, &sn, &cs);
                float r1 = (t1 * cs - t2 * sn) * sc_;
                float r2 = (t2 * cs + t1 * sn) * sc_;
                if (nt < NH) {
                    long o = ((long)(b * NH + nt) * S + s) * HD;
                    Ch[o + d]      = __float2half_rn(r1);
                    Ch[o + d + 64] = __float2half_rn(r2);
                } else {
                    long o = ((long)(b * NKV + nt - NH) * S + s) * HD;
                    Ck[o + d]      = __float2half_rn(r1);
                    Ck[o + d + 64] = __float2half_rn(r2);
                }
            }
        } else {
            const int h = nt - NH - NKV;
            for (int i = tid; i < 128 * 128; i += 256) {
                int d  = i >> 7;
                int sc2 = i & 127;
                float v = st[sc2 * EPS_ST + d];
                int grow = m0 + sc2;
                int b = grow / S, s = grow - b * S;
                Cvt[((long)(b * NKV + h) * HD + d) * S + s] = __float2half_rn(v);
            }
        }
        return;
    }

    if (MODE == 3) {
        #pragma unroll
        for (int ma = 0; ma < 4; ma++) {
            #pragma unroll
            for (int na = 0; na < 4; na += 2) {
                long r0 = m0 + wm + ma * 16 + erow;
                int cc = n0 + wn + na * 8 + ecol;
                long j = ((long)(cc >> 4) << 3) + (cc & 7);
                __half2 h0 = __floats2half2_rn(silu_mul(acc[ma][na][0], acc[ma][na+1][0]),
                                               silu_mul(acc[ma][na][1], acc[ma][na+1][1]));
                __half2 h1 = __floats2half2_rn(silu_mul(acc[ma][na][2], acc[ma][na+1][2]),
                                               silu_mul(acc[ma][na][3], acc[ma][na+1][3]));
                *(__half2*)&Ch[r0 * (long)FFI + j] = h0;
                *(__half2*)&Ch[(r0 + 8) * (long)FFI + j] = h1;
            }
        }
        return;
    }

    #pragma unroll
    for (int ma = 0; ma < 4; ma++) {
        #pragma unroll
        for (int na = 0; na < 4; na++) {
            long r0 = m0 + wm + ma * 16 + erow;
            long cc = n0 + wn + na * 8 + ecol;
            float v00 = acc[ma][na][0], v01 = acc[ma][na][1];
            float v10 = acc[ma][na][2], v11 = acc[ma][na][3];
            if (RES) {
                const float2 q0 = *(const float2*)&R[r0 * ldc + cc];
                const float2 q1 = *(const float2*)&R[(r0 + 8) * ldc + cc];
                v00 += q0.x; v01 += q0.y; v10 += q1.x; v11 += q1.y;
            }
            float2 w0 = {v00, v01}, w1 = {v10, v11};
            *(float2*)&Cf[r0 * ldc + cc] = w0;
            *(float2*)&Cf[(r0 + 8) * ldc + cc] = w1;
        }
    }
}

// ================= fused flash attention =================
#define FT_STRIDE 136
#define FT_TILEB (128 * FT_STRIDE * 2)   /* 34816 */
#define FT_SMEM  (5 * FT_TILEB)          /* 174080 */

__global__ void __launch_bounds__(256, 1)
fattn(const __half* __restrict__ Qg, const __half* __restrict__ Kg,
      const __half* __restrict__ Vg, __half* __restrict__ AO, int S)
{
    extern __shared__ char sm[];
    const uint32_t sb = smem_u32(sm);
    const int tid = threadIdx.x, wid = tid >> 5, lane = tid & 31;
    const int mt = gridDim.x - 1 - blockIdx.x;
    const int m0 = mt * 128;
    const int z = blockIdx.z;
    const int b = z >> 4, h = z & 15;
    const __half* Qp = Qg + ((long)z * S + m0) * HD;
    const __half* Kp = Kg + (long)(b * NKV + (h >> 2)) * S * HD;
    const __half* Vp = Vg + (long)(b * NKV + (h >> 2)) * HD * S;

    const uint32_t sQ = sb;

    #pragma unroll
    for (int i = 0; i < 8; i++) {
        int idx = tid + 256 * i;
        int r = idx >> 4, c = idx & 15;
        cp16(sQ + (r * FT_STRIDE + c * 8) * 2, Qp + (long)r * HD + c * 8);
    }
    cp_commit();

    auto load_kv = [&](int st, int j) {
        const uint32_t sK = sb + FT_TILEB + st * 2 * FT_TILEB;
        const uint32_t sV = sK + FT_TILEB;
        const __half* ks = Kp + (long)(j * 128) * HD;
        const __half* vs = Vp + j * 128;
        #pragma unroll
        for (int i = 0; i < 8; i++) {
            int idx = tid + 256 * i;
            int r = idx >> 4, c = idx & 15;
            cp16(sK + (r * FT_STRIDE + c * 8) * 2, ks + (long)r * HD + c * 8);
        }
        #pragma unroll
        for (int i = 0; i < 8; i++) {
            int idx = tid + 256 * i;
            int r = idx >> 4, c = idx & 15;
            cp16(sV + (r * FT_STRIDE + c * 8) * 2, vs + (long)r * S + c * 8);
        }
        cp_commit();
    };

    const int J = mt + 1;
    load_kv(0, 0);

    const int wm = wid * 16;
    const int alr = lane & 15, alc = (lane >> 4) * 8;
    const int blr = lane & 7, bhalf = (lane >> 3) & 1, bquad = (lane >> 4) * 8;
    const int r0 = lane >> 2, c0 = (lane & 3) * 2;

    float acc_o[16][4];
    #pragma unroll
    for (int i = 0; i < 16; i++)
        #pragma unroll
        for (int q = 0; q < 4; q++) acc_o[i][q] = 0.f;
    float rm0 = -1e30f, rm1 = -1e30f, rs0 = 0.f, rs1 = 0.f;

    for (int j = 0; j < J; j++) {
        const int st = j & 1;
        if (j + 1 < J) { load_kv(st ^ 1, j + 1); cp_wait1(); }
        else           { cp_wait0(); }
        __syncthreads();
        const uint32_t sK = sb + FT_TILEB + st * 2 * FT_TILEB;
        const uint32_t sV = sK + FT_TILEB;

        float accs[16][4];
        #pragma unroll
        for (int i = 0; i < 16; i++)
            #pragma unroll
            for (int q = 0; q < 4; q++) accs[i][q] = 0.f;
        #pragma unroll
        for (int kt = 0; kt < 8; kt++) {
            uint32_t aa[4];
            ldm_x4(aa, sQ + ((wm + alr) * FT_STRIDE + kt * 16 + alc) * 2);
            #pragma unroll
            for (int np = 0; np < 8; np++) {
                uint32_t t4[4];
                ldm_x4(t4, sK + ((np * 16 + bquad + blr) * FT_STRIDE + kt * 16 + bhalf * 8) * 2);
                uint32_t b0[2] = { t4[0], t4[1] }, b1[2] = { t4[2], t4[3] };
                mma16816h(accs[2*np],   aa, b0);
                mma16816h(accs[2*np+1], aa, b1);
            }
        }
        if (j == mt) {
            const int row0 = wm + r0, row1 = row0 + 8;
            #pragma unroll
            for (int na = 0; na < 16; na++) {
                int col = na * 8 + c0;
                if (col     > row0) accs[na][0] = -1e30f;
                if (col + 1 > row0) accs[na][1] = -1e30f;
                if (col     > row1) accs[na][2] = -1e30f;
                if (col + 1 > row1) accs[na][3] = -1e30f;
            }
        }
        float mt0 = -1e30f, mt1 = -1e30f;
        #pragma unroll
        for (int na = 0; na < 16; na++) {
            mt0 = fmaxf(mt0, fmaxf(accs[na][0], accs[na][1]));
            mt1 = fmaxf(mt1, fmaxf(accs[na][2], accs[na][3]));
        }
        mt0 = fmaxf(mt0, __shfl_xor_sync(0xffffffffu, mt0, 1));
        mt0 = fmaxf(mt0, __shfl_xor_sync(0xffffffffu, mt0, 2));
        mt1 = fmaxf(mt1, __shfl_xor_sync(0xffffffffu, mt1, 1));
        mt1 = fmaxf(mt1, __shfl_xor_sync(0xffffffffu, mt1, 2));
        float nm0 = fmaxf(rm0, mt0), nm1 = fmaxf(rm1, mt1);
        float corr0 = __expf(rm0 - nm0), corr1 = __expf(rm1 - nm1);
        rm0 = nm0; rm1 = nm1;
        float st0 = 0.f, st1 = 0.f;
        uint32_t pa[8][4];
        #pragma unroll
        for (int kf = 0; kf < 8; kf++) {
            float p00 = __expf(accs[2*kf][0]   - nm0), p01 = __expf(accs[2*kf][1]   - nm0);
            float p10 = __expf(accs[2*kf][2]   - nm1), p11 = __expf(accs[2*kf][3]   - nm1);
            float q00 = __expf(accs[2*kf+1][0] - nm0), q01 = __expf(accs[2*kf+1][1] - nm0);
            float q10 = __expf(accs[2*kf+1][2] - nm1), q11 = __expf(accs[2*kf+1][3] - nm1);
            st0 += p00 + p01 + q00 + q01;
            st1 += p10 + p11 + q10 + q11;
            pa[kf][0] = pack_h2(p00, p01);
            pa[kf][1] = pack_h2(p10, p11);
            pa[kf][2] = pack_h2(q00, q01);
            pa[kf][3] = pack_h2(q10, q11);
        }
        st0 += __shfl_xor_sync(0xffffffffu, st0, 1);
        st0 += __shfl_xor_sync(0xffffffffu, st0, 2);
        st1 += __shfl_xor_sync(0xffffffffu, st1, 1);
        st1 += __shfl_xor_sync(0xffffffffu, st1, 2);
        rs0 = rs0 * corr0 + st0;
        rs1 = rs1 * corr1 + st1;
        #pragma unroll
        for (int na = 0; na < 16; na++) {
            acc_o[na][0] *= corr0; acc_o[na][1] *= corr0;
            acc_o[na][2] *= corr1; acc_o[na][3] *= corr1;
        }
        #pragma unroll
        for (int kf = 0; kf < 8; kf++) {
            #pragma unroll
            for (int np = 0; np < 8; np++) {
                uint32_t t4[4];
                ldm_x4(t4, sV + ((np * 16 + bquad + blr) * FT_STRIDE + kf * 16 + bhalf * 8) * 2);
                uint32_t b0[2] = { t4[0], t4[1] }, b1[2] = { t4[2], t4[3] };
                mma16816h(acc_o[2*np],   pa[kf], b0);
                mma16816h(acc_o[2*np+1], pa[kf], b1);
            }
        }
        __syncthreads();
    }

    const float i0 = 1.f / rs0, i1 = 1.f / rs1;
    const int s0 = m0 + wm + r0;
    const long base0 = ((long)b * S + s0) * HIDD + h * HD;
    const long base1 = ((long)b * S + s0 + 8) * HIDD + h * HD;
    #pragma unroll
    for (int na = 0; na < 16; na++) {
        int d = na * 8 + c0;
        __half2 h0 = __floats2half2_rn(acc_o[na][0] * i0, acc_o[na][1] * i0);
        __half2 h1 = __floats2half2_rn(acc_o[na][2] * i1, acc_o[na][3] * i1);
        *(__half2*)&AO[base0 + d] = h0;
        *(__half2*)&AO[base1 + d] = h1;
    }
}

// ================= block reductions =================
__device__ __forceinline__ float block_sum(float v) {
    #pragma unroll
    for (int o = 16; o > 0; o >>= 1) v += __shfl_xor_sync(0xffffffffu, v, o);
    __shared__ float sh[8]; __shared__ float total;
    int w = threadIdx.x >> 5, l = threadIdx.x & 31;
    if (l == 0) sh[w] = v;
    __syncthreads();
    if (threadIdx.x == 0) { float s = 0.f; for (int i = 0; i < 8; i++) s += sh[i]; total = s; }
    __syncthreads();
    return total;
}

// ================= elementwise =================
__global__ void rmsnorm_h_kernel(const float* __restrict__ x, const float* __restrict__ w,
                                 __half* __restrict__ out) {
    long row = blockIdx.x;
    const float4* xr4 = (const float4*)(x + row * HIDD);
    const float4* w4  = (const float4*)w;
    float s = 0.f;
    #pragma unroll 2
    for (int i = threadIdx.x; i < HIDD / 4; i += 256) {
        float4 v = xr4[i];
        s += v.x * v.x + v.y * v.y + v.z * v.z + v.w * v.w;
    }
    s = block_sum(s);
    float inv = rsqrtf(s / (float)HIDD + 1e-6f);
    __half2* o2 = (__half2*)(out + row * HIDD);
    #pragma unroll 2
    for (int i = threadIdx.x; i < HIDD / 4; i += 256) {
        float4 v = xr4[i];
        float4 ww = w4[i];
        o2[2*i]   = __floats2half2_rn(v.x * inv * ww.x, v.y * inv * ww.y);
        o2[2*i+1] = __floats2half2_rn(v.z * inv * ww.z, v.w * inv * ww.w);
    }
}

__device__ __forceinline__ uint4 cvt8(const float* p) {
    float4 a = *(const float4*)p, b = *(const float4*)(p + 4);
    uint4 o;
    o.x = pack_h2(a.x, a.y); o.y = pack_h2(a.z, a.w);
    o.z = pack_h2(b.x, b.y); o.w = pack_h2(b.z, b.w);
    return o;
}

// merged weight convert: all four weights in one launch, 16 halves per thread.
// regions (in 16-half units): wqkv | wo | dn | gu(interleave)
#define N16_QKV ((long)HIDD * QKVW / 16)
#define N16_WO  ((long)HIDD * HIDD / 16)
#define N16_DN  ((long)FFI  * HIDD / 16)
#define N16_GU  ((long)HIDD * FFI / 8)
#define N16_ALL (N16_QKV + N16_WO + N16_DN + N16_GU)

__global__ void convAll_kernel(const float* __restrict__ Wqkv, const float* __restrict__ Wo,
                               const float* __restrict__ Wdn, const float* __restrict__ Wgu,
                               __half* __restrict__ Tqkv, __half* __restrict__ To,
                               __half* __restrict__ Tdn, __half* __restrict__ Tgu) {
    long i = (long)blockIdx.x * 256 + threadIdx.x;
    if (i >= N16_ALL) return;
    if (i < N16_QKV) {
        *(uint4*)&Tqkv[i * 16]     = cvt8(Wqkv + i * 16);
        *(uint4*)&Tqkv[i * 16 + 8] = cvt8(Wqkv + i * 16 + 8);
        return;
    }
    i -= N16_QKV;
    if (i < N16_WO) {
        *(uint4*)&To[i * 16]     = cvt8(Wo + i * 16);
        *(uint4*)&To[i * 16 + 8] = cvt8(Wo + i * 16 + 8);
        return;
    }
    i -= N16_WO;
    if (i < N16_DN) {
        *(uint4*)&Tdn[i * 16]     = cvt8(Wdn + i * 16);
        *(uint4*)&Tdn[i * 16 + 8] = cvt8(Wdn + i * 16 + 8);
        return;
    }
    i -= N16_DN;
    // gate_up 8-block interleave: out[row][16j..16j+7]=gate block, [16j+8..]=up block
    long row = i / (FFI / 8);
    int  j   = (int)(i % (FFI / 8));
    const float* base = Wgu + row * (2L * FFI);
    __half* dst = Tgu + row * (2L * FFI) + j * 16;
    *(uint4*)dst       = cvt8(base + j * 8);
    *(uint4*)(dst + 8) = cvt8(base + FFI + j * 8);
}

// ================= host launcher =================
extern "C" void kernel_launch(void* const* d_in, const int* in_sizes, int n_in,
                              void* d_out, int out_size) {
    const float* x         = (const float*)d_in[0];
    const float* ln1_w     = (const float*)d_in[1];
    const float* wqkv      = (const float*)d_in[2];
    const float* wo        = (const float*)d_in[3];
    const float* ln2_w     = (const float*)d_in[4];
    const float* w_gate_up = (const float*)d_in[5];
    const float* w_down    = (const float*)d_in[6];
    const int*   pos       = (const int*)d_in[7];
    float* out = (float*)d_out;

    const int S  = in_sizes[7];                 // 1024
    const long BS = (long)in_sizes[0] / HIDD;   // 4096
    const int Bb = (int)(BS / S);               // 4

    float *pH1;
    cudaGetSymbolAddress((void**)&pH1,  g_h1);
    __half *pH,*pAO,*pACT,*pQ,*pK,*pVt;
    __half *pQKVH,*pWOH,*pGUH,*pDNH;
    cudaGetSymbolAddress((void**)&pH, g_h);
    cudaGetSymbolAddress((void**)&pAO, g_ao);
    cudaGetSymbolAddress((void**)&pACT, g_act);
    cudaGetSymbolAddress((void**)&pQ, g_q);
    cudaGetSymbolAddress((void**)&pK, g_k);
    cudaGetSymbolAddress((void**)&pVt, g_vt);
    cudaGetSymbolAddress((void**)&pQKVH, g_wqkvH);
    cudaGetSymbolAddress((void**)&pWOH, g_woH);
    cudaGetSymbolAddress((void**)&pGUH, g_guH);
    cudaGetSymbolAddress((void**)&pDNH, g_dnH);

    cudaFuncSetAttribute(hgemm<0,false>, cudaFuncAttributeMaxDynamicSharedMemorySize, HG_SMEM);
    cudaFuncSetAttribute(hgemm<0,true>,  cudaFuncAttributeMaxDynamicSharedMemorySize, HG_SMEM);
    cudaFuncSetAttribute(hgemm<3,false>, cudaFuncAttributeMaxDynamicSharedMemorySize, HG_SMEM);
    cudaFuncSetAttribute(hgemm<4,false>, cudaFuncAttributeMaxDynamicSharedMemorySize, HG_SMEM);
    cudaFuncSetAttribute(fattn, cudaFuncAttributeMaxDynamicSharedMemorySize, FT_SMEM);

    const float inv_sqrt_d = 0.08838834764831843f;

    // merged weight convert
    convAll_kernel<<<(unsigned)((N16_ALL + 255) / 256), 256>>>(
        wqkv, wo, w_down, w_gate_up, pQKVH, pWOH, pDNH, pGUH);

    // 1. h = rmsnorm(x) -> fp16
    rmsnorm_h_kernel<<<(int)BS, 256>>>(x, ln1_w, pH);

    // 2+3. qkv GEMM with fused RoPE/split/v-transpose epilogue (q pre-scaled by 1/sqrt(D))
    hgemm<4,false><<<dim3((int)(BS/128), QKVW/128, 1), 256, HG_SMEM>>>(
        pH, pQKVH, nullptr, nullptr, pQ, pK, pVt, pos,
        HIDD, QKVW, 0, inv_sqrt_d, S);

    // 4-6. fused flash attention -> ao fp16 [b,s,h*d]
    fattn<<<dim3(S/128, 1, Bb*NH), 256, FT_SMEM>>>(pQ, pK, pVt, pAO, S);

    // 7. h1 = x + attnout @ wo
    hgemm<0,true><<<dim3((int)(BS/128), HIDD/128, 1), 256, HG_SMEM>>>(
        pAO, pWOH, x, pH1, nullptr, nullptr, nullptr, nullptr,
        HIDD, HIDD, HIDD, 0.f, S);

    // 8. h2 = rmsnorm(h1)
    rmsnorm_h_kernel<<<(int)BS, 256>>>(pH1, ln2_w, pH);

    // 9+10. act = silu(gate)*up fused into gate_up GEMM -> fp16
    hgemm<3,false><<<dim3((int)(BS/128), 2*FFI/128, 1), 256, HG_SMEM>>>(
        pH, pGUH, nullptr, nullptr, pACT, nullptr, nullptr, nullptr,
        HIDD, 2*FFI, 0, 0.f, S);

    // 11. out = h1 + act @ w_down
    hgemm<0,true><<<dim3((int)(BS/128), HIDD/128, 1), 256, HG_SMEM>>>(
        pACT, pDNH, pH1, out, nullptr, nullptr, nullptr, nullptr,
        FFI, HIDD, HIDD, 0.f, S);
}

// round 17
// speedup vs baseline: 1.0304x; 1.0304x over previous
#include <cuda_runtime.h>
#include <cuda_fp16.h>
#include <math.h>
#include <stdint.h>

#define NH   16
#define NKV  4
#define HD   128
#define HIDD 2048
#define FFI  8192
#define QKVW ((NH + 2*NKV) * HD)   /* 3072 */

// ================= scratch (B=4, S=1024) =================
static __device__ float g_h1[4096L * HIDD];

static __device__ __half g_h[4096L * HIDD];
static __device__ __half g_ao[4096L * HIDD];
static __device__ __half g_act[4096L * FFI];
static __device__ __half g_q[(long)4*NH*1024*HD];
static __device__ __half g_k[(long)4*NKV*1024*HD];
static __device__ __half g_vt[(long)4*NKV*HD*1024];
static __device__ __half g_wqkvH[(long)HIDD * QKVW];   /* [K,N] native */
static __device__ __half g_woH[(long)HIDD * HIDD];
static __device__ __half g_guH[(long)HIDD * 2*FFI];    /* [K,N], gate/up 8-block interleaved */
static __device__ __half g_dnH[(long)FFI * HIDD];

// ================= PTX helpers =================
__device__ __forceinline__ uint32_t smem_u32(const void* p) {
    uint32_t a;
    asm("{ .reg .u64 t; cvta.to.shared.u64 t, %1; cvt.u32.u64 %0, t; }" : "=r"(a) : "l"(p));
    return a;
}
__device__ __forceinline__ void cp16(uint32_t dst, const void* src) {
    asm volatile("cp.async.cg.shared.global [%0], [%1], 16;" :: "r"(dst), "l"(src));
}
__device__ __forceinline__ void cp_commit() { asm volatile("cp.async.commit_group;"); }
__device__ __forceinline__ void cp_wait1() { asm volatile("cp.async.wait_group 1;"); }
__device__ __forceinline__ void cp_wait0() { asm volatile("cp.async.wait_group 0;"); }

__device__ __forceinline__ void ldm_x4(uint32_t* r, uint32_t addr) {
    asm volatile("ldmatrix.sync.aligned.m8n8.x4.shared.b16 {%0,%1,%2,%3}, [%4];"
        : "=r"(r[0]), "=r"(r[1]), "=r"(r[2]), "=r"(r[3]) : "r"(addr));
}
__device__ __forceinline__ void ldm_x4t(uint32_t* r, uint32_t addr) {
    asm volatile("ldmatrix.sync.aligned.m8n8.x4.trans.shared.b16 {%0,%1,%2,%3}, [%4];"
        : "=r"(r[0]), "=r"(r[1]), "=r"(r[2]), "=r"(r[3]) : "r"(addr));
}
__device__ __forceinline__ void mma16816h(float* d, const uint32_t* a, const uint32_t* b) {
    asm volatile("mma.sync.aligned.m16n8k16.row.col.f32.f16.f16.f32 "
        "{%0,%1,%2,%3}, {%4,%5,%6,%7}, {%8,%9}, {%0,%1,%2,%3};"
        : "+f"(d[0]), "+f"(d[1]), "+f"(d[2]), "+f"(d[3])
        : "r"(a[0]), "r"(a[1]), "r"(a[2]), "r"(a[3]), "r"(b[0]), "r"(b[1]));
}
__device__ __forceinline__ float silu_mul(float g, float u) {
    return (g / (1.f + __expf(-g))) * u;
}
__device__ __forceinline__ uint32_t pack_h2(float a, float b) {
    __half2 h = __floats2half2_rn(a, b);
    return *(uint32_t*)&h;
}

// ================= fp16 GEMM (A: [M,K] row-major; B: [K,N] row-major via ldmatrix.trans) =================
// MODE 0: weights (fp32 out, optional residual, block swizzle)
// MODE 3: gate_up (8-block-interleaved B cols; epilogue silu(gate)*up -> fp16, block swizzle)
// MODE 4: qkv     (epilogue stages tile to smem; RoPE+split q/k (+1/sqrt(D) on q), transpose v)
#define SAS 72
#define ATILEB (128 * SAS * 2)    /* 18432 */
#define BSTR 136                  /* B smem row stride (halves) */
#define BTILEB (64 * BSTR * 2)    /* 17408 */
#define STAGE (ATILEB + BTILEB)   /* 35840 */
#define HG_SMEM (2 * STAGE)       /* 71680, 2-stage (validated R15) */
#define EPS_ST 133                /* fp32 staging stride; 128*133*4=68096 <= 71680 */

template<int MODE, bool RES>
__global__ void __launch_bounds__(256, 2)
hgemm(const __half* __restrict__ A, const __half* __restrict__ B,
      const float* __restrict__ R, float* __restrict__ Cf, __half* __restrict__ Ch,
      __half* __restrict__ Ck, __half* __restrict__ Cvt, const int* __restrict__ pos,
      int K, int ldb, int ldc, float qscale, int S)
{
    extern __shared__ char sm[];
    const uint32_t sbase = smem_u32(sm);
    const int tid = threadIdx.x;

    int m0, n0;
    {
        int lin = blockIdx.y * gridDim.x + blockIdx.x;
        int grpSize = gridDim.x * 8;
        int grp = lin / grpSize, rem = lin % grpSize;
        m0 = (rem >> 3) * 128;
        n0 = (grp * 8 + (rem & 7)) * 128;
    }

    const int NB = K >> 6;
    const int wid = tid >> 5, lane = tid & 31;
    const int wm = (wid >> 2) * 64;
    const int wn = (wid & 3) * 32;

    const __half* Asrc = A + (long)m0 * K;
    const __half* Bsrc = B + n0;

    const int alr = lane & 15, alc = (lane >> 4) * 8;
    const int blr = lane & 7;
    const int bhalf = (lane >> 3) & 1;
    const int bquad = (lane >> 4) * 8;

    float acc[4][4][4];
    #pragma unroll
    for (int i = 0; i < 4; i++)
        #pragma unroll
        for (int j = 0; j < 4; j++)
            #pragma unroll
            for (int q = 0; q < 4; q++) acc[i][j][q] = 0.f;

    auto load_stage = [&](int s, int blk) {
        const long kb = (long)blk << 6;
        const uint32_t dA = sbase + s * STAGE;
        #pragma unroll
        for (int i = 0; i < 4; i++) {
            int idx = tid + 256 * i;
            int r = idx >> 3, c = idx & 7;
            cp16(dA + (r * SAS + c * 8) * 2, Asrc + kb + (long)r * K + c * 8);
        }
        const uint32_t dB = dA + ATILEB;
        #pragma unroll
        for (int i = 0; i < 4; i++) {
            int idx = tid + 256 * i;
            int r = idx >> 4, c = idx & 15;   // r: k-row 0..63, c: n-chunk
            cp16(dB + (r * BSTR + c * 8) * 2, Bsrc + (kb + r) * (long)ldb + c * 8);
        }
        cp_commit();
    };

    load_stage(0, 0);

    for (int blk = 0; blk < NB; blk++) {
        const int s = blk & 1;
        if (blk + 1 < NB) { load_stage(s ^ 1, blk + 1); cp_wait1(); }
        else              { cp_wait0(); }
        __syncthreads();

        const uint32_t sA_ = sbase + s * STAGE;
        const uint32_t sB_ = sA_ + ATILEB;

        #pragma unroll
        for (int kt = 0; kt < 4; kt++) {
            uint32_t aa[4][4], bb[4][2];
            #pragma unroll
            for (int ma = 0; ma < 4; ma++) {
                uint32_t ao = ((wm + ma * 16 + alr) * SAS + kt * 16 + alc) * 2;
                ldm_x4(aa[ma], sA_ + ao);
            }
            #pragma unroll
            for (int np = 0; np < 2; np++) {
                uint32_t bo = ((kt * 16 + bhalf * 8 + blr) * BSTR + wn + np * 16 + bquad) * 2;
                uint32_t t4[4];
                ldm_x4t(t4, sB_ + bo);
                bb[np*2+0][0] = t4[0]; bb[np*2+0][1] = t4[1];
                bb[np*2+1][0] = t4[2]; bb[np*2+1][1] = t4[3];
            }
            #pragma unroll
            for (int ma = 0; ma < 4; ma++)
                #pragma unroll
                for (int na = 0; na < 4; na++)
                    mma16816h(acc[ma][na], aa[ma], bb[na]);
        }
        __syncthreads();
    }

    const int erow = lane >> 2, ecol = (lane & 3) * 2;

    if (MODE == 4) {
        float* st = (float*)sm;
        #pragma unroll
        for (int ma = 0; ma < 4; ma++) {
            #pragma unroll
            for (int na = 0; na < 4; na++) {
                int rr = wm + ma * 16 + erow;
                int cc = wn + na * 8 + ecol;
                st[rr * EPS_ST + cc]           = acc[ma][na][0];
                st[rr * EPS_ST + cc + 1]       = acc[ma][na][1];
                st[(rr + 8) * EPS_ST + cc]     = acc[ma][na][2];
                st[(rr + 8) * EPS_ST + cc + 1] = acc[ma][na][3];
            }
        }
        __syncthreads();
        const int nt = n0 >> 7;          // 0..15 q, 16..19 k, 20..23 v
        if (nt < NH + NKV) {
            const float sc_ = (nt < NH) ? qscale : 1.f;
            for (int i = tid; i < 128 * 64; i += 256) {
                int rr = i >> 6;
                int d  = i & 63;
                float t1 = st[rr * EPS_ST + d];
                float t2 = st[rr * EPS_ST + d + 64];
                int grow = m0 + rr;
                int b = grow / S, s = grow - b * S;
                float invf = __powf(10000.f, -(float)d * (1.f/64.f));
                float ang = (float)pos[s] * invf;
                float sn, cs;
                __sincosf(ang, &sn, &cs);
                float r1 = (t1 * cs - t2 * sn) * sc_;
                float r2 = (t2 * cs + t1 * sn) * sc_;
                if (nt < NH) {
                    long o = ((long)(b * NH + nt) * S + s) * HD;
                    Ch[o + d]      = __float2half_rn(r1);
                    Ch[o + d + 64] = __float2half_rn(r2);
                } else {
                    long o = ((long)(b * NKV + nt - NH) * S + s) * HD;
                    Ck[o + d]      = __float2half_rn(r1);
                    Ck[o + d + 64] = __float2half_rn(r2);
                }
            }
        } else {
            const int h = nt - NH - NKV;
            for (int i = tid; i < 128 * 128; i += 256) {
                int d  = i >> 7;
                int sc2 = i & 127;
                float v = st[sc2 * EPS_ST + d];
                int grow = m0 + sc2;
                int b = grow / S, s = grow - b * S;
                Cvt[((long)(b * NKV + h) * HD + d) * S + s] = __float2half_rn(v);
            }
        }
        return;
    }

    if (MODE == 3) {
        #pragma unroll
        for (int ma = 0; ma < 4; ma++) {
            #pragma unroll
            for (int na = 0; na < 4; na += 2) {
                long r0 = m0 + wm + ma * 16 + erow;
                int cc = n0 + wn + na * 8 + ecol;
                long j = ((long)(cc >> 4) << 3) + (cc & 7);
                __half2 h0 = __floats2half2_rn(silu_mul(acc[ma][na][0], acc[ma][na+1][0]),
                                               silu_mul(acc[ma][na][1], acc[ma][na+1][1]));
                __half2 h1 = __floats2half2_rn(silu_mul(acc[ma][na][2], acc[ma][na+1][2]),
                                               silu_mul(acc[ma][na][3], acc[ma][na+1][3]));
                *(__half2*)&Ch[r0 * (long)FFI + j] = h0;
                *(__half2*)&Ch[(r0 + 8) * (long)FFI + j] = h1;
            }
        }
        return;
    }

    #pragma unroll
    for (int ma = 0; ma < 4; ma++) {
        #pragma unroll
        for (int na = 0; na < 4; na++) {
            long r0 = m0 + wm + ma * 16 + erow;
            long cc = n0 + wn + na * 8 + ecol;
            float v00 = acc[ma][na][0], v01 = acc[ma][na][1];
            float v10 = acc[ma][na][2], v11 = acc[ma][na][3];
            if (RES) {
                const float2 q0 = *(const float2*)&R[r0 * ldc + cc];
                const float2 q1 = *(const float2*)&R[(r0 + 8) * ldc + cc];
                v00 += q0.x; v01 += q0.y; v10 += q1.x; v11 += q1.y;
            }
            float2 w0 = {v00, v01}, w1 = {v10, v11};
            *(float2*)&Cf[r0 * ldc + cc] = w0;
            *(float2*)&Cf[(r0 + 8) * ldc + cc] = w1;
        }
    }
}

// ================= fused flash attention =================
#define FT_STRIDE 136
#define FT_TILEB (128 * FT_STRIDE * 2)   /* 34816 */
#define FT_SMEM  (5 * FT_TILEB)          /* 174080 */

__global__ void __launch_bounds__(256, 1)
fattn(const __half* __restrict__ Qg, const __half* __restrict__ Kg,
      const __half* __restrict__ Vg, __half* __restrict__ AO, int S)
{
    extern __shared__ char sm[];
    const uint32_t sb = smem_u32(sm);
    const int tid = threadIdx.x, wid = tid >> 5, lane = tid & 31;
    const int mt = gridDim.x - 1 - blockIdx.x;
    const int m0 = mt * 128;
    const int z = blockIdx.z;
    const int b = z >> 4, h = z & 15;
    const __half* Qp = Qg + ((long)z * S + m0) * HD;
    const __half* Kp = Kg + (long)(b * NKV + (h >> 2)) * S * HD;
    const __half* Vp = Vg + (long)(b * NKV + (h >> 2)) * HD * S;

    const uint32_t sQ = sb;

    #pragma unroll
    for (int i = 0; i < 8; i++) {
        int idx = tid + 256 * i;
        int r = idx >> 4, c = idx & 15;
        cp16(sQ + (r * FT_STRIDE + c * 8) * 2, Qp + (long)r * HD + c * 8);
    }
    cp_commit();

    auto load_kv = [&](int st, int j) {
        const uint32_t sK = sb + FT_TILEB + st * 2 * FT_TILEB;
        const uint32_t sV = sK + FT_TILEB;
        const __half* ks = Kp + (long)(j * 128) * HD;
        const __half* vs = Vp + j * 128;
        #pragma unroll
        for (int i = 0; i < 8; i++) {
            int idx = tid + 256 * i;
            int r = idx >> 4, c = idx & 15;
            cp16(sK + (r * FT_STRIDE + c * 8) * 2, ks + (long)r * HD + c * 8);
        }
        #pragma unroll
        for (int i = 0; i < 8; i++) {
            int idx = tid + 256 * i;
            int r = idx >> 4, c = idx & 15;
            cp16(sV + (r * FT_STRIDE + c * 8) * 2, vs + (long)r * S + c * 8);
        }
        cp_commit();
    };

    const int J = mt + 1;
    load_kv(0, 0);

    const int wm = wid * 16;
    const int alr = lane & 15, alc = (lane >> 4) * 8;
    const int blr = lane & 7, bhalf = (lane >> 3) & 1, bquad = (lane >> 4) * 8;
    const int r0 = lane >> 2, c0 = (lane & 3) * 2;

    float acc_o[16][4];
    #pragma unroll
    for (int i = 0; i < 16; i++)
        #pragma unroll
        for (int q = 0; q < 4; q++) acc_o[i][q] = 0.f;
    float rm0 = -1e30f, rm1 = -1e30f, rs0 = 0.f, rs1 = 0.f;

    for (int j = 0; j < J; j++) {
        const int st = j & 1;
        if (j + 1 < J) { load_kv(st ^ 1, j + 1); cp_wait1(); }
        else           { cp_wait0(); }
        __syncthreads();
        const uint32_t sK = sb + FT_TILEB + st * 2 * FT_TILEB;
        const uint32_t sV = sK + FT_TILEB;

        float accs[16][4];
        #pragma unroll
        for (int i = 0; i < 16; i++)
            #pragma unroll
            for (int q = 0; q < 4; q++) accs[i][q] = 0.f;
        #pragma unroll
        for (int kt = 0; kt < 8; kt++) {
            uint32_t aa[4];
            ldm_x4(aa, sQ + ((wm + alr) * FT_STRIDE + kt * 16 + alc) * 2);
            #pragma unroll
            for (int np = 0; np < 8; np++) {
                uint32_t t4[4];
                ldm_x4(t4, sK + ((np * 16 + bquad + blr) * FT_STRIDE + kt * 16 + bhalf * 8) * 2);
                uint32_t b0[2] = { t4[0], t4[1] }, b1[2] = { t4[2], t4[3] };
                mma16816h(accs[2*np],   aa, b0);
                mma16816h(accs[2*np+1], aa, b1);
            }
        }
        if (j == mt) {
            const int row0 = wm + r0, row1 = row0 + 8;
            #pragma unroll
            for (int na = 0; na < 16; na++) {
                int col = na * 8 + c0;
                if (col     > row0) accs[na][0] = -1e30f;
                if (col + 1 > row0) accs[na][1] = -1e30f;
                if (col     > row1) accs[na][2] = -1e30f;
                if (col + 1 > row1) accs[na][3] = -1e30f;
            }
        }
        float mt0 = -1e30f, mt1 = -1e30f;
        #pragma unroll
        for (int na = 0; na < 16; na++) {
            mt0 = fmaxf(mt0, fmaxf(accs[na][0], accs[na][1]));
            mt1 = fmaxf(mt1, fmaxf(accs[na][2], accs[na][3]));
        }
        mt0 = fmaxf(mt0, __shfl_xor_sync(0xffffffffu, mt0, 1));
        mt0 = fmaxf(mt0, __shfl_xor_sync(0xffffffffu, mt0, 2));
        mt1 = fmaxf(mt1, __shfl_xor_sync(0xffffffffu, mt1, 1));
        mt1 = fmaxf(mt1, __shfl_xor_sync(0xffffffffu, mt1, 2));
        float nm0 = fmaxf(rm0, mt0), nm1 = fmaxf(rm1, mt1);
        float corr0 = __expf(rm0 - nm0), corr1 = __expf(rm1 - nm1);
        rm0 = nm0; rm1 = nm1;
        float st0 = 0.f, st1 = 0.f;
        uint32_t pa[8][4];
        #pragma unroll
        for (int kf = 0; kf < 8; kf++) {
            float p00 = __expf(accs[2*kf][0]   - nm0), p01 = __expf(accs[2*kf][1]   - nm0);
            float p10 = __expf(accs[2*kf][2]   - nm1), p11 = __expf(accs[2*kf][3]   - nm1);
            float q00 = __expf(accs[2*kf+1][0] - nm0), q01 = __expf(accs[2*kf+1][1] - nm0);
            float q10 = __expf(accs[2*kf+1][2] - nm1), q11 = __expf(accs[2*kf+1][3] - nm1);
            st0 += p00 + p01 + q00 + q01;
            st1 += p10 + p11 + q10 + q11;
            pa[kf][0] = pack_h2(p00, p01);
            pa[kf][1] = pack_h2(p10, p11);
            pa[kf][2] = pack_h2(q00, q01);
            pa[kf][3] = pack_h2(q10, q11);
        }
        st0 += __shfl_xor_sync(0xffffffffu, st0, 1);
        st0 += __shfl_xor_sync(0xffffffffu, st0, 2);
        st1 += __shfl_xor_sync(0xffffffffu, st1, 1);
        st1 += __shfl_xor_sync(0xffffffffu, st1, 2);
        rs0 = rs0 * corr0 + st0;
        rs1 = rs1 * corr1 + st1;
        #pragma unroll
        for (int na = 0; na < 16; na++) {
            acc_o[na][0] *= corr0; acc_o[na][1] *= corr0;
            acc_o[na][2] *= corr1; acc_o[na][3] *= corr1;
        }
        #pragma unroll
        for (int kf = 0; kf < 8; kf++) {
            #pragma unroll
            for (int np = 0; np < 8; np++) {
                uint32_t t4[4];
                ldm_x4(t4, sV + ((np * 16 + bquad + blr) * FT_STRIDE + kf * 16 + bhalf * 8) * 2);
                uint32_t b0[2] = { t4[0], t4[1] }, b1[2] = { t4[2], t4[3] };
                mma16816h(acc_o[2*np],   pa[kf], b0);
                mma16816h(acc_o[2*np+1], pa[kf], b1);
            }
        }
        __syncthreads();
    }

    const float i0 = 1.f / rs0, i1 = 1.f / rs1;
    const int s0 = m0 + wm + r0;
    const long base0 = ((long)b * S + s0) * HIDD + h * HD;
    const long base1 = ((long)b * S + s0 + 8) * HIDD + h * HD;
    #pragma unroll
    for (int na = 0; na < 16; na++) {
        int d = na * 8 + c0;
        __half2 h0 = __floats2half2_rn(acc_o[na][0] * i0, acc_o[na][1] * i0);
        __half2 h1 = __floats2half2_rn(acc_o[na][2] * i1, acc_o[na][3] * i1);
        *(__half2*)&AO[base0 + d] = h0;
        *(__half2*)&AO[base1 + d] = h1;
    }
}

// ================= block reductions =================
__device__ __forceinline__ float block_sum(float v) {
    #pragma unroll
    for (int o = 16; o > 0; o >>= 1) v += __shfl_xor_sync(0xffffffffu, v, o);
    __shared__ float sh[8]; __shared__ float total;
    int w = threadIdx.x >> 5, l = threadIdx.x & 31;
    if (l == 0) sh[w] = v;
    __syncthreads();
    if (threadIdx.x == 0) { float s = 0.f; for (int i = 0; i < 8; i++) s += sh[i]; total = s; }
    __syncthreads();
    return total;
}

// ================= elementwise =================
__global__ void rmsnorm_h_kernel(const float* __restrict__ x, const float* __restrict__ w,
                                 __half* __restrict__ out) {
    long row = blockIdx.x;
    const float4* xr4 = (const float4*)(x + row * HIDD);
    const float4* w4  = (const float4*)w;
    float s = 0.f;
    #pragma unroll 2
    for (int i = threadIdx.x; i < HIDD / 4; i += 256) {
        float4 v = xr4[i];
        s += v.x * v.x + v.y * v.y + v.z * v.z + v.w * v.w;
    }
    s = block_sum(s);
    float inv = rsqrtf(s / (float)HIDD + 1e-6f);
    __half2* o2 = (__half2*)(out + row * HIDD);
    #pragma unroll 2
    for (int i = threadIdx.x; i < HIDD / 4; i += 256) {
        float4 v = xr4[i];
        float4 ww = w4[i];
        o2[2*i]   = __floats2half2_rn(v.x * inv * ww.x, v.y * inv * ww.y);
        o2[2*i+1] = __floats2half2_rn(v.z * inv * ww.z, v.w * inv * ww.w);
    }
}

__device__ __forceinline__ uint4 cvt8(const float* p) {
    float4 a = *(const float4*)p, b = *(const float4*)(p + 4);
    uint4 o;
    o.x = pack_h2(a.x, a.y); o.y = pack_h2(a.z, a.w);
    o.z = pack_h2(b.x, b.y); o.w = pack_h2(b.z, b.w);
    return o;
}

// merged weight convert: all four weights in one launch, 16 halves per thread.
#define N16_QKV ((long)HIDD * QKVW / 16)
#define N16_WO  ((long)HIDD * HIDD / 16)
#define N16_DN  ((long)FFI  * HIDD / 16)
#define N16_GU  ((long)HIDD * FFI / 8)
#define N16_ALL (N16_QKV + N16_WO + N16_DN + N16_GU)

__global__ void convAll_kernel(const float* __restrict__ Wqkv, const float* __restrict__ Wo,
                               const float* __restrict__ Wdn, const float* __restrict__ Wgu,
                               __half* __restrict__ Tqkv, __half* __restrict__ To,
                               __half* __restrict__ Tdn, __half* __restrict__ Tgu) {
    long i = (long)blockIdx.x * 256 + threadIdx.x;
    if (i >= N16_ALL) return;
    if (i < N16_QKV) {
        *(uint4*)&Tqkv[i * 16]     = cvt8(Wqkv + i * 16);
        *(uint4*)&Tqkv[i * 16 + 8] = cvt8(Wqkv + i * 16 + 8);
        return;
    }
    i -= N16_QKV;
    if (i < N16_WO) {
        *(uint4*)&To[i * 16]     = cvt8(Wo + i * 16);
        *(uint4*)&To[i * 16 + 8] = cvt8(Wo + i * 16 + 8);
        return;
    }
    i -= N16_WO;
    if (i < N16_DN) {
        *(uint4*)&Tdn[i * 16]     = cvt8(Wdn + i * 16);
        *(uint4*)&Tdn[i * 16 + 8] = cvt8(Wdn + i * 16 + 8);
        return;
    }
    i -= N16_DN;
    // gate_up 8-block interleave: out[row][16j..16j+7]=gate block, [16j+8..]=up block
    long row = i / (FFI / 8);
    int  j   = (int)(i % (FFI / 8));
    const float* base = Wgu + row * (2L * FFI);
    __half* dst = Tgu + row * (2L * FFI) + j * 16;
    *(uint4*)dst       = cvt8(base + j * 8);
    *(uint4*)(dst + 8) = cvt8(base + FFI + j * 8);
}

// ================= host launcher =================
extern "C" void kernel_launch(void* const* d_in, const int* in_sizes, int n_in,
                              void* d_out, int out_size) {
    const float* x         = (const float*)d_in[0];
    const float* ln1_w     = (const float*)d_in[1];
    const float* wqkv      = (const float*)d_in[2];
    const float* wo        = (const float*)d_in[3];
    const float* ln2_w     = (const float*)d_in[4];
    const float* w_gate_up = (const float*)d_in[5];
    const float* w_down    = (const float*)d_in[6];
    const int*   pos       = (const int*)d_in[7];
    float* out = (float*)d_out;

    const int S  = in_sizes[7];                 // 1024
    const long BS = (long)in_sizes[0] / HIDD;   // 4096
    const int Bb = (int)(BS / S);               // 4

    float *pH1;
    cudaGetSymbolAddress((void**)&pH1,  g_h1);
    __half *pH,*pAO,*pACT,*pQ,*pK,*pVt;
    __half *pQKVH,*pWOH,*pGUH,*pDNH;
    cudaGetSymbolAddress((void**)&pH, g_h);
    cudaGetSymbolAddress((void**)&pAO, g_ao);
    cudaGetSymbolAddress((void**)&pACT, g_act);
    cudaGetSymbolAddress((void**)&pQ, g_q);
    cudaGetSymbolAddress((void**)&pK, g_k);
    cudaGetSymbolAddress((void**)&pVt, g_vt);
    cudaGetSymbolAddress((void**)&pQKVH, g_wqkvH);
    cudaGetSymbolAddress((void**)&pWOH, g_woH);
    cudaGetSymbolAddress((void**)&pGUH, g_guH);
    cudaGetSymbolAddress((void**)&pDNH, g_dnH);

    cudaFuncSetAttribute(hgemm<0,false>, cudaFuncAttributeMaxDynamicSharedMemorySize, HG_SMEM);
    cudaFuncSetAttribute(hgemm<0,true>,  cudaFuncAttributeMaxDynamicSharedMemorySize, HG_SMEM);
    cudaFuncSetAttribute(hgemm<3,false>, cudaFuncAttributeMaxDynamicSharedMemorySize, HG_SMEM);
    cudaFuncSetAttribute(hgemm<4,false>, cudaFuncAttributeMaxDynamicSharedMemorySize, HG_SMEM);
    cudaFuncSetAttribute(fattn, cudaFuncAttributeMaxDynamicSharedMemorySize, FT_SMEM);

    const float inv_sqrt_d = 0.08838834764831843f;

    // merged weight convert
    convAll_kernel<<<(unsigned)((N16_ALL + 255) / 256), 256>>>(
        wqkv, wo, w_down, w_gate_up, pQKVH, pWOH, pDNH, pGUH);

    // 1. h = rmsnorm(x) -> fp16
    rmsnorm_h_kernel<<<(int)BS, 256>>>(x, ln1_w, pH);

    // 2+3. qkv GEMM with fused RoPE/split/v-transpose epilogue (q pre-scaled by 1/sqrt(D))
    hgemm<4,false><<<dim3((int)(BS/128), QKVW/128, 1), 256, HG_SMEM>>>(
        pH, pQKVH, nullptr, nullptr, pQ, pK, pVt, pos,
        HIDD, QKVW, 0, inv_sqrt_d, S);

    // 4-6. fused flash attention -> ao fp16 [b,s,h*d]
    fattn<<<dim3(S/128, 1, Bb*NH), 256, FT_SMEM>>>(pQ, pK, pVt, pAO, S);

    // 7. h1 = x + attnout @ wo
    hgemm<0,true><<<dim3((int)(BS/128), HIDD/128, 1), 256, HG_SMEM>>>(
        pAO, pWOH, x, pH1, nullptr, nullptr, nullptr, nullptr,
        HIDD, HIDD, HIDD, 0.f, S);

    // 8. h2 = rmsnorm(h1)
    rmsnorm_h_kernel<<<(int)BS, 256>>>(pH1, ln2_w, pH);

    // 9+10. act = silu(gate)*up fused into gate_up GEMM -> fp16
    hgemm<3,false><<<dim3((int)(BS/128), 2*FFI/128, 1), 256, HG_SMEM>>>(
        pH, pGUH, nullptr, nullptr, pACT, nullptr, nullptr, nullptr,
        HIDD, 2*FFI, 0, 0.f, S);

    // 11. out = h1 + act @ w_down
    hgemm<0,true><<<dim3((int)(BS/128), HIDD/128, 1), 256, HG_SMEM>>>(
        pACT, pDNH, pH1, out, nullptr, nullptr, nullptr, nullptr,
        FFI, HIDD, HIDD, 0.f, S);
}